// round 1
// baseline (speedup 1.0000x reference)
#include <cuda_runtime.h>
#include <cuda_bf16.h>
#include <cmath>

#define T_  200
#define B_  256
#define E_  128
#define H_  50
#define G4  200            // 4*H
#define M_  (T_ * B_)      // 51200 rows

// Scratch (static device globals -- allocation-free)
__device__ float g_xproj[M_ * G4];   // [T,B,4H] flat: ((t*B + b)*200 + n)
__device__ float g_hs[M_ * H_];      // [T,B,H]  flat: ((t*B + b)*50 + k)

// ---------------------------------------------------------------------------
// K1: x_proj[r, n] = sum_e embed[tokens[r], e] * W_ih[n, e] + b_ih[n] + b_hh[n]
// Tiled fp32 GEMM with gathered A. BM=64 rows/CTA, BN=200 (full), BK=32.
// threads=256: warp (8) = row group of 8, lane (32) = n-quad q0=lane, q1=lane+32 (lane<18)
// ---------------------------------------------------------------------------
__global__ __launch_bounds__(256) void k1_xproj(
    const int*   __restrict__ tokens,
    const float* __restrict__ emb,
    const float* __restrict__ Wih,
    const float* __restrict__ bih,
    const float* __restrict__ bhh)
{
    __shared__ __align__(16) float Bs[32][200];  // Bs[kk][n] = Wih[n][k0+kk]
    __shared__ __align__(16) float As[32][68];   // As[kk][m] = emb[tok[m]][k0+kk] (pad 68)
    __shared__ int   toks[64];
    __shared__ float bsum[200];

    const int tid  = threadIdx.x;
    const int lane = tid & 31;
    const int warp = tid >> 5;          // row sub-block: rows warp*8 .. warp*8+7
    const int row0 = blockIdx.x * 64;

    if (tid < 64)  toks[tid] = tokens[row0 + tid];
    if (tid < 200) bsum[tid] = bih[tid] + bhh[tid];

    float acc0[8][4];
    float acc1[8][4];
#pragma unroll
    for (int m = 0; m < 8; m++)
#pragma unroll
        for (int j = 0; j < 4; j++) { acc0[m][j] = 0.f; acc1[m][j] = 0.f; }

    __syncthreads();

    for (int k0 = 0; k0 < 128; k0 += 32) {
        // Load W tile (transposed): 6400 floats
#pragma unroll
        for (int i = tid; i < 6400; i += 256) {
            int n  = i >> 5;
            int kk = i & 31;
            Bs[kk][n] = Wih[n * 128 + k0 + kk];
        }
        // Gather A tile: 64 rows x 32 k
#pragma unroll
        for (int i = tid; i < 2048; i += 256) {
            int m  = i >> 5;
            int kk = i & 31;
            As[kk][m] = emb[toks[m] * 128 + k0 + kk];
        }
        __syncthreads();

#pragma unroll 8
        for (int kk = 0; kk < 32; kk++) {
            const float4 A0 = *reinterpret_cast<const float4*>(&As[kk][warp * 8]);
            const float4 A1 = *reinterpret_cast<const float4*>(&As[kk][warp * 8 + 4]);
            float a[8] = {A0.x, A0.y, A0.z, A0.w, A1.x, A1.y, A1.z, A1.w};
            const float4 Bq0 = *reinterpret_cast<const float4*>(&Bs[kk][lane * 4]);
#pragma unroll
            for (int m = 0; m < 8; m++) {
                acc0[m][0] = fmaf(a[m], Bq0.x, acc0[m][0]);
                acc0[m][1] = fmaf(a[m], Bq0.y, acc0[m][1]);
                acc0[m][2] = fmaf(a[m], Bq0.z, acc0[m][2]);
                acc0[m][3] = fmaf(a[m], Bq0.w, acc0[m][3]);
            }
            if (lane < 18) {
                const float4 Bq1 = *reinterpret_cast<const float4*>(&Bs[kk][128 + lane * 4]);
#pragma unroll
                for (int m = 0; m < 8; m++) {
                    acc1[m][0] = fmaf(a[m], Bq1.x, acc1[m][0]);
                    acc1[m][1] = fmaf(a[m], Bq1.y, acc1[m][1]);
                    acc1[m][2] = fmaf(a[m], Bq1.z, acc1[m][2]);
                    acc1[m][3] = fmaf(a[m], Bq1.w, acc1[m][3]);
                }
            }
        }
        __syncthreads();
    }

    // Store with bias
    const float4 bq0 = *reinterpret_cast<const float4*>(&bsum[lane * 4]);
    float4 bq1 = make_float4(0.f, 0.f, 0.f, 0.f);
    if (lane < 18) bq1 = *reinterpret_cast<const float4*>(&bsum[128 + lane * 4]);
#pragma unroll
    for (int m = 0; m < 8; m++) {
        const int row = row0 + warp * 8 + m;
        float4 o;
        o.x = acc0[m][0] + bq0.x;
        o.y = acc0[m][1] + bq0.y;
        o.z = acc0[m][2] + bq0.z;
        o.w = acc0[m][3] + bq0.w;
        *reinterpret_cast<float4*>(&g_xproj[row * 200 + lane * 4]) = o;
        if (lane < 18) {
            float4 o1;
            o1.x = acc1[m][0] + bq1.x;
            o1.y = acc1[m][1] + bq1.y;
            o1.z = acc1[m][2] + bq1.z;
            o1.w = acc1[m][3] + bq1.w;
            *reinterpret_cast<float4*>(&g_xproj[row * 200 + 128 + lane * 4]) = o1;
        }
    }
}

// ---------------------------------------------------------------------------
// K2: the recurrence. 128 CTAs x 512 threads; group g = tid>>8 owns batch
// element b = blockIdx.x*2 + g. Thread n (<200) computes gate n each step,
// holding W_hh[n][:] in registers; h broadcast from smem via float4.
// Two named barriers (per 256-thread group) per step.
// ---------------------------------------------------------------------------
__device__ __forceinline__ void group_bar(int g) {
    asm volatile("bar.sync %0, %1;" :: "r"(g + 1), "r"(256) : "memory");
}

__global__ __launch_bounds__(512) void k2_lstm(const float* __restrict__ Whh)
{
    __shared__ __align__(16) float h_s[2][56];
    __shared__ float gates_s[2][200];

    const int tid = threadIdx.x;
    const int g   = tid >> 8;
    const int n   = tid & 255;
    const int b   = blockIdx.x * 2 + g;
    const bool act = (n < 200);

    float w[52];
#pragma unroll
    for (int k = 0; k < 52; k++) w[k] = 0.f;
    if (act) {
#pragma unroll
        for (int k = 0; k < 50; k++) w[k] = Whh[n * 50 + k];
    }
    if (n < 56) h_s[g][n] = 0.f;
    __syncthreads();

    float c  = 0.f;
    float xp = act ? g_xproj[(0 * B_ + b) * 200 + n] : 0.f;

    for (int t = 0; t < T_; t++) {
        // prefetch next step's x_proj element (consumed next iteration)
        float xpn = 0.f;
        if (act && (t + 1) < T_) xpn = g_xproj[((t + 1) * B_ + b) * 200 + n];

        if (act) {
            float acc = xp;
            const float4* h4 = reinterpret_cast<const float4*>(h_s[g]);
#pragma unroll
            for (int kq = 0; kq < 13; kq++) {
                const float4 hv = h4[kq];
                acc = fmaf(hv.x, w[4 * kq + 0], acc);
                acc = fmaf(hv.y, w[4 * kq + 1], acc);
                acc = fmaf(hv.z, w[4 * kq + 2], acc);
                acc = fmaf(hv.w, w[4 * kq + 3], acc);
            }
            gates_s[g][n] = acc;
        }
        group_bar(g);

        if (n < 50) {
            const float iv = gates_s[g][n];
            const float fv = gates_s[g][n + 50];
            const float gv = gates_s[g][n + 100];
            const float ov = gates_s[g][n + 150];
            const float si = 1.f / (1.f + __expf(-iv));
            const float sf = 1.f / (1.f + __expf(-fv));
            const float so = 1.f / (1.f + __expf(-ov));
            c = sf * c + si * tanhf(gv);
            const float hn = so * tanhf(c);
            h_s[g][n] = hn;
            g_hs[(t * B_ + b) * 50 + n] = hn;
        }
        group_bar(g);
        xp = xpn;
    }
}

// ---------------------------------------------------------------------------
// K3: head. out[r, :] = relu(h_r @ W1^T + b1) @ W2^T + b2, flat over 51200 rows.
// ---------------------------------------------------------------------------
__global__ __launch_bounds__(256) void k3_head(
    const float* __restrict__ W1, const float* __restrict__ b1,
    const float* __restrict__ W2, const float* __restrict__ b2,
    float* __restrict__ out)
{
    __shared__ float sW1[16 * 50];
    __shared__ float sW2[9 * 16];
    __shared__ float sb1[16];
    __shared__ float sb2[9];

    const int tid = threadIdx.x;
    for (int i = tid; i < 800; i += 256) sW1[i] = W1[i];
    if (tid < 144) sW2[tid] = W2[tid];
    if (tid < 16)  sb1[tid] = b1[tid];
    if (tid < 9)   sb2[tid] = b2[tid];
    __syncthreads();

    const int r = blockIdx.x * 256 + tid;   // exactly 51200 threads total
    const float* __restrict__ hrow = &g_hs[r * 50];

    float hv[50];
#pragma unroll
    for (int k = 0; k < 50; k++) hv[k] = hrow[k];

    float z[16];
#pragma unroll
    for (int j = 0; j < 16; j++) {
        float a = sb1[j];
#pragma unroll
        for (int k = 0; k < 50; k++) a = fmaf(hv[k], sW1[j * 50 + k], a);
        z[j] = fmaxf(a, 0.f);
    }
#pragma unroll
    for (int p = 0; p < 9; p++) {
        float o = sb2[p];
#pragma unroll
        for (int j = 0; j < 16; j++) o = fmaf(z[j], sW2[p * 16 + j], o);
        out[r * 9 + p] = o;
    }
}

// ---------------------------------------------------------------------------
extern "C" void kernel_launch(void* const* d_in, const int* in_sizes, int n_in,
                              void* d_out, int out_size)
{
    const int*   tokens = (const int*)  d_in[0];
    const float* emb    = (const float*)d_in[1];
    const float* Wih    = (const float*)d_in[2];
    const float* Whh    = (const float*)d_in[3];
    const float* bih    = (const float*)d_in[4];
    const float* bhh    = (const float*)d_in[5];
    const float* W1     = (const float*)d_in[6];
    const float* b1     = (const float*)d_in[7];
    const float* W2     = (const float*)d_in[8];
    const float* b2     = (const float*)d_in[9];
    float* out = (float*)d_out;

    k1_xproj<<<M_ / 64, 256>>>(tokens, emb, Wih, bih, bhh);
    k2_lstm <<<B_ / 2, 512>>>(Whh);
    k3_head <<<M_ / 256, 256>>>(W1, b1, W2, b2, out);
}

// round 2
// speedup vs baseline: 1.4819x; 1.4819x over previous
#include <cuda_runtime.h>
#include <cuda_bf16.h>
#include <cmath>

#define T_  200
#define B_  256
#define E_  128
#define H_  50
#define M_  (T_ * B_)      // 51200 rows

// Scratch (static device globals -- allocation-free)
__device__ float g_xproj[M_ * 200];  // [T,B,4H]
__device__ float g_hs[M_ * H_];      // [T,B,H]

// ---------------- f32x2 packed fp32 helpers (Blackwell) ----------------
__device__ __forceinline__ unsigned long long fma2(unsigned long long a,
                                                   unsigned long long b,
                                                   unsigned long long c) {
    unsigned long long d;
    asm("fma.rn.f32x2 %0, %1, %2, %3;" : "=l"(d) : "l"(a), "l"(b), "l"(c));
    return d;
}
__device__ __forceinline__ float2 u2f(unsigned long long v) {
    float2 r;
    asm("mov.b64 {%0, %1}, %2;" : "=f"(r.x), "=f"(r.y) : "l"(v));
    return r;
}
__device__ __forceinline__ unsigned long long f2u(float lo, float hi) {
    unsigned long long v;
    asm("mov.b64 %0, {%1, %2};" : "=l"(v) : "f"(lo), "f"(hi));
    return v;
}
__device__ __forceinline__ unsigned smem_u32(const void* p) {
    return (unsigned)__cvta_generic_to_shared(p);
}
__device__ __forceinline__ void cp16(unsigned dst, const void* src) {
    asm volatile("cp.async.cg.shared.global [%0], [%1], 16;" :: "r"(dst), "l"(src));
}

// ---------------------------------------------------------------------------
// K1: x_proj = gather(emb, tokens) @ Wih^T + (bih + bhh)
// Persistent: 148 CTAs x 512 threads. Full Wih in smem (pair-interleaved:
// word(k,n) = (k>>1)*400 + 2n + (k&1)), A tiles double-buffered via cp.async.
// Thread: warp owns 4 rows; lane owns col pairs {2l,2l+1}+0/64/128/(192,l<4).
// Inner loop over 64 k-pairs, f32x2 FMAs (2 k-terms per instr, summed at end).
// ---------------------------------------------------------------------------
#define K1_BM   64
#define K1_ASZ  (K1_BM * 128)        // words per A buffer
#define K1_BSZ  25600                // words for Bs
#define K1_SMEM_WORDS (K1_BSZ + 2*K1_ASZ + 200)

__global__ __launch_bounds__(512, 1) void k1_xproj(
    const int*   __restrict__ tokens,
    const float* __restrict__ emb,
    const float* __restrict__ Wih,
    const float* __restrict__ bih,
    const float* __restrict__ bhh)
{
    extern __shared__ __align__(16) float sm[];
    float* Bs   = sm;                       // 25600 words
    float* As   = sm + K1_BSZ;              // 2 x 8192 words
    float* bsum = sm + K1_BSZ + 2*K1_ASZ;   // 200 words

    const int tid  = threadIdx.x;
    const int lane = tid & 31;
    const int warp = tid >> 5;

    // Stage full Wih (pair-interleaved along K) -- once per CTA.
    for (int i = tid; i < K1_BSZ; i += 512) {
        const int n = i >> 7;
        const int k = i & 127;
        Bs[(k >> 1) * 400 + 2 * n + (k & 1)] = Wih[i];
    }
    if (tid < 200) bsum[tid] = bih[tid] + bhh[tid];

    const int cta   = blockIdx.x;
    const int nblk  = (cta < 60) ? 6 : 5;
    const int start = cta * 5 + ((cta < 60) ? cta : 60);

    // Prologue: issue A tile for block 0 into buffer 0.
    {
        const int row0 = start * K1_BM;
        for (int i = tid; i < 2048; i += 512) {
            const int m  = i >> 5;
            const int ch = i & 31;
            const int tok = tokens[row0 + m];
            cp16(smem_u32(&As[m * 128 + ch * 4]),
                 emb + (size_t)tok * 128 + ch * 4);
        }
        asm volatile("cp.async.commit_group;");
    }

    for (int b = 0; b < nblk; b++) {
        asm volatile("cp.async.wait_group 0;");
        __syncthreads();   // A tile b ready (and Bs on first iter)

        if (b + 1 < nblk) {
            const int row0 = (start + b + 1) * K1_BM;
            float* dst = As + ((b + 1) & 1) * K1_ASZ;
            for (int i = tid; i < 2048; i += 512) {
                const int m  = i >> 5;
                const int ch = i & 31;
                const int tok = tokens[row0 + m];
                cp16(smem_u32(&dst[m * 128 + ch * 4]),
                     emb + (size_t)tok * 128 + ch * 4);
            }
            asm volatile("cp.async.commit_group;");
        }

        const float* Ab = As + (b & 1) * K1_ASZ;

        unsigned long long acc[4][8];
#pragma unroll
        for (int m = 0; m < 4; m++)
#pragma unroll
            for (int j = 0; j < 8; j++) acc[m][j] = 0ull;

#pragma unroll 4
        for (int kk2 = 0; kk2 < 64; kk2++) {
            unsigned long long a[4];
#pragma unroll
            for (int m = 0; m < 4; m++)
                a[m] = *reinterpret_cast<const unsigned long long*>(
                    &Ab[(warp * 4 + m) * 128 + 2 * kk2]);

            const float* brow = &Bs[kk2 * 400 + 4 * lane];
            const ulonglong2 q0 = *reinterpret_cast<const ulonglong2*>(brow);
            const ulonglong2 q1 = *reinterpret_cast<const ulonglong2*>(brow + 128);
            const ulonglong2 q2 = *reinterpret_cast<const ulonglong2*>(brow + 256);
#pragma unroll
            for (int m = 0; m < 4; m++) {
                acc[m][0] = fma2(a[m], q0.x, acc[m][0]);
                acc[m][1] = fma2(a[m], q0.y, acc[m][1]);
                acc[m][2] = fma2(a[m], q1.x, acc[m][2]);
                acc[m][3] = fma2(a[m], q1.y, acc[m][3]);
                acc[m][4] = fma2(a[m], q2.x, acc[m][4]);
                acc[m][5] = fma2(a[m], q2.y, acc[m][5]);
            }
            if (lane < 4) {
                const ulonglong2 q3 = *reinterpret_cast<const ulonglong2*>(brow + 384);
#pragma unroll
                for (int m = 0; m < 4; m++) {
                    acc[m][6] = fma2(a[m], q3.x, acc[m][6]);
                    acc[m][7] = fma2(a[m], q3.y, acc[m][7]);
                }
            }
        }

        // Epilogue: horizontal-add k-halves, add bias, store.
        const int r0 = (start + b) * K1_BM + warp * 4;
#pragma unroll
        for (int m = 0; m < 4; m++) {
            float* orow = g_xproj + (size_t)(r0 + m) * 200;
#pragma unroll
            for (int cc = 0; cc < 3; cc++) {
                const float2 s0 = u2f(acc[m][2 * cc]);
                const float2 s1 = u2f(acc[m][2 * cc + 1]);
                const int col = cc * 64 + 2 * lane;
                float2 o;
                o.x = s0.x + s0.y + bsum[col];
                o.y = s1.x + s1.y + bsum[col + 1];
                *reinterpret_cast<float2*>(orow + col) = o;
            }
            if (lane < 4) {
                const float2 s0 = u2f(acc[m][6]);
                const float2 s1 = u2f(acc[m][7]);
                const int col = 192 + 2 * lane;
                float2 o;
                o.x = s0.x + s0.y + bsum[col];
                o.y = s1.x + s1.y + bsum[col + 1];
                *reinterpret_cast<float2*>(orow + col) = o;
            }
        }
    }
}

// ---------------------------------------------------------------------------
// K2: recurrence. 128 CTAs x 512 threads; group g owns batch b = blk*2+g.
// Thread n<200 computes gate n: 25 f32x2 FMAs into 4 independent accumulators
// (breaks the serial chain). Fast clamped activations.
// ---------------------------------------------------------------------------
__global__ __launch_bounds__(512, 1) void k2_lstm(const float* __restrict__ Whh)
{
    __shared__ __align__(16) float h_s[2][52];
    __shared__ float gates_s[2][200];

    const int tid = threadIdx.x;
    const int g   = tid >> 8;
    const int n   = tid & 255;
    const int b   = blockIdx.x * 2 + g;
    const bool act = (n < 200);

    unsigned long long w2[25];
    if (act) {
        const float2* wr = reinterpret_cast<const float2*>(Whh + n * 50);
#pragma unroll
        for (int q = 0; q < 25; q++) {
            const float2 v = wr[q];
            w2[q] = f2u(v.x, v.y);
        }
    }
    if (n < 52) h_s[g][n] = 0.f;
    __syncthreads();

    float c  = 0.f;
    float xp = act ? g_xproj[(size_t)b * 200 + n] : 0.f;

    for (int t = 0; t < T_; t++) {
        float xpn = 0.f;
        if (act && (t + 1) < T_) xpn = g_xproj[(size_t)((t + 1) * B_ + b) * 200 + n];

        if (act) {
            const unsigned long long* h2 =
                reinterpret_cast<const unsigned long long*>(h_s[g]);
            unsigned long long a0 = 0ull, a1 = 0ull, a2 = 0ull, a3 = 0ull;
#pragma unroll
            for (int q = 0; q < 24; q += 4) {
                a0 = fma2(h2[q],     w2[q],     a0);
                a1 = fma2(h2[q + 1], w2[q + 1], a1);
                a2 = fma2(h2[q + 2], w2[q + 2], a2);
                a3 = fma2(h2[q + 3], w2[q + 3], a3);
            }
            a0 = fma2(h2[24], w2[24], a0);
            const float2 s0 = u2f(a0), s1 = u2f(a1), s2 = u2f(a2), s3 = u2f(a3);
            gates_s[g][n] = xp + ((s0.x + s0.y) + (s1.x + s1.y))
                               + ((s2.x + s2.y) + (s3.x + s3.y));
        }
        asm volatile("bar.sync %0, 256;" :: "r"(g + 1) : "memory");

        if (n < 50) {
            const float iv = gates_s[g][n];
            const float fv = gates_s[g][n + 50];
            float       gv = gates_s[g][n + 100];
            const float ov = gates_s[g][n + 150];
            const float si = __fdividef(1.f, 1.f + __expf(-iv));
            const float sf = __fdividef(1.f, 1.f + __expf(-fv));
            const float so = __fdividef(1.f, 1.f + __expf(-ov));
            gv = fminf(fmaxf(gv, -15.f), 15.f);
            const float eg = __expf(-2.f * gv);
            const float tg = __fdividef(1.f - eg, 1.f + eg);
            c = fmaf(sf, c, si * tg);
            const float cc2 = fminf(fmaxf(c, -15.f), 15.f);
            const float ec  = __expf(-2.f * cc2);
            const float tc  = __fdividef(1.f - ec, 1.f + ec);
            const float hn  = so * tc;
            h_s[g][n] = hn;
            g_hs[(size_t)(t * B_ + b) * 50 + n] = hn;
        }
        asm volatile("bar.sync %0, 256;" :: "r"(g + 1) : "memory");
        xp = xpn;
    }
}

// ---------------------------------------------------------------------------
// K3: head. out[r,:] = relu(h_r @ W1^T + b1) @ W2^T + b2 (flat over 51200 rows)
// ---------------------------------------------------------------------------
__global__ __launch_bounds__(256) void k3_head(
    const float* __restrict__ W1, const float* __restrict__ b1,
    const float* __restrict__ W2, const float* __restrict__ b2,
    float* __restrict__ out)
{
    __shared__ float sW1[16 * 50];
    __shared__ float sW2[9 * 16];
    __shared__ float sb1[16];
    __shared__ float sb2[9];

    const int tid = threadIdx.x;
    for (int i = tid; i < 800; i += 256) sW1[i] = W1[i];
    if (tid < 144) sW2[tid] = W2[tid];
    if (tid < 16)  sb1[tid] = b1[tid];
    if (tid < 9)   sb2[tid] = b2[tid];
    __syncthreads();

    const int r = blockIdx.x * 256 + tid;
    const float* __restrict__ hrow = &g_hs[(size_t)r * 50];

    float hv[50];
#pragma unroll
    for (int k = 0; k < 50; k++) hv[k] = hrow[k];

    float z[16];
#pragma unroll
    for (int j = 0; j < 16; j++) {
        float a = sb1[j];
#pragma unroll
        for (int k = 0; k < 50; k++) a = fmaf(hv[k], sW1[j * 50 + k], a);
        z[j] = fmaxf(a, 0.f);
    }
#pragma unroll
    for (int p = 0; p < 9; p++) {
        float o = sb2[p];
#pragma unroll
        for (int j = 0; j < 16; j++) o = fmaf(z[j], sW2[p * 16 + j], o);
        out[r * 9 + p] = o;
    }
}

// ---------------------------------------------------------------------------
extern "C" void kernel_launch(void* const* d_in, const int* in_sizes, int n_in,
                              void* d_out, int out_size)
{
    const int*   tokens = (const int*)  d_in[0];
    const float* emb    = (const float*)d_in[1];
    const float* Wih    = (const float*)d_in[2];
    const float* Whh    = (const float*)d_in[3];
    const float* bih    = (const float*)d_in[4];
    const float* bhh    = (const float*)d_in[5];
    const float* W1     = (const float*)d_in[6];
    const float* b1     = (const float*)d_in[7];
    const float* W2     = (const float*)d_in[8];
    const float* b2     = (const float*)d_in[9];
    float* out = (float*)d_out;

    const int k1_smem = K1_SMEM_WORDS * 4;   // 168,736 bytes
    cudaFuncSetAttribute(k1_xproj, cudaFuncAttributeMaxDynamicSharedMemorySize,
                         k1_smem);

    k1_xproj<<<148, 512, k1_smem>>>(tokens, emb, Wih, bih, bhh);
    k2_lstm <<<B_ / 2, 512>>>(Whh);
    k3_head <<<M_ / 256, 256>>>(W1, b1, W2, b2, out);
}